// round 15
// baseline (speedup 1.0000x reference)
#include <cuda_runtime.h>
#include <cuda_bf16.h>
#include <math.h>

// ----------------------------------------------------------------------------
// Problem constants
// ----------------------------------------------------------------------------
#define BATCH   2
#define DIM     512
#define HEADS   8
#define DHEAD   64
#define FRAMES  8
#define HH      32
#define WW      32
#define HW      1024            // H*W
#define NTOK    16384           // B*F*H*W
#define SEQ_S   16              // B*F spatial sequences
#define SEQ_T   2048            // B*H*W temporal sequences
#define CPB     256
#define FFI     1365            // FF_INNER
#define FFI_P   1408            // padded to mult of 16 (and 128-friendly)
#define FF2     2730            // 2*FF_INNER
#define FF2_P   2816            // padded to mult of 128
#define C1      683             // (FFI+1)//2
#define SCALE_ATTN 0.125f       // 64^-0.5

// ----------------------------------------------------------------------------
// Device scratch (device globals: allocation-free per harness rules)
// ----------------------------------------------------------------------------
__device__ float g_xs  [NTOK * DIM];        // tokens, spatial layout
__device__ float g_xn  [NTOK * DIM];        // rms-normed tokens
__device__ float g_q   [NTOK * DIM];
__device__ float g_kv  [NTOK * 2 * DIM];
__device__ float g_o   [NTOK * DIM];
__device__ float g_res1[NTOK * DIM];        // after spatial attn (spatial layout)
__device__ float g_res2[NTOK * DIM];        // after temporal attn (spatial layout)
__device__ float g_ffd [NTOK * DIM];        // after FF (+res), pre-transpose
__device__ float g_hdn [NTOK * FF2_P];      // FF hidden (padded)
__device__ float g_y   [NTOK * FFI_P];      // geglu output (padded)
__device__ float g_yn  [NTOK * FFI_P];      // shifted + rms-normed (padded)
__device__ float g_wp1 [DIM  * FF2_P];      // padded ff_win
__device__ float g_wp2 [FFI_P * DIM];       // padded ff_wout
__device__ float g_sptab[3969 * 8];
__device__ float g_tptab[15 * 8];

// ----------------------------------------------------------------------------
// Transposes (b: [512][8192] <-> [8192][512])
// ----------------------------------------------------------------------------
__global__ void transpose_in_kernel(const float* __restrict__ x, float* __restrict__ xs) {
    __shared__ float tile[32][33];
    int b  = blockIdx.z;
    int p0 = blockIdx.x * 32;      // fhw
    int c0 = blockIdx.y * 32;      // channel
    int tx = threadIdx.x, ty = threadIdx.y;
    const float* in = x + (long)b * DIM * 8192;
#pragma unroll
    for (int i = 0; i < 32; i += 8)
        tile[ty + i][tx] = in[(long)(c0 + ty + i) * 8192 + p0 + tx];
    __syncthreads();
#pragma unroll
    for (int i = 0; i < 32; i += 8)
        xs[((long)b * 8192 + p0 + ty + i) * DIM + c0 + tx] = tile[tx][ty + i];
}

__global__ void transpose_out_kernel(const float* __restrict__ ffd, float* __restrict__ out) {
    __shared__ float tile[32][33];
    int b  = blockIdx.z;
    int p0 = blockIdx.x * 32;
    int c0 = blockIdx.y * 32;
    int tx = threadIdx.x, ty = threadIdx.y;
#pragma unroll
    for (int i = 0; i < 32; i += 8)
        tile[ty + i][tx] = ffd[((long)b * 8192 + p0 + ty + i) * DIM + c0 + tx];
    __syncthreads();
    float* ob = out + (long)b * DIM * 8192;
#pragma unroll
    for (int i = 0; i < 32; i += 8)
        ob[(long)(c0 + ty + i) * 8192 + p0 + tx] = tile[tx][ty + i];
}

// ----------------------------------------------------------------------------
// CPB bias MLPs
// ----------------------------------------------------------------------------
__device__ __forceinline__ float silu_f(float z) { return z / (1.f + __expf(-z)); }

__global__ __launch_bounds__(256) void cpb2d_kernel(
    const float* __restrict__ w1, const float* __restrict__ b1,
    const float* __restrict__ w2, const float* __restrict__ b2,
    const float* __restrict__ w3, const float* __restrict__ b3,
    float* __restrict__ tab)
{
    __shared__ float h1s[8][CPB];
    __shared__ float h2s[8][CPB];
    int t = threadIdx.x;
    int rbase = blockIdx.x * 8;
    float w1a = w1[t], w1b = w1[CPB + t], bb1 = b1[t];
#pragma unroll
    for (int r = 0; r < 8; r++) {
        int rr = min(rbase + r, 3968);
        float gy = (float)(rr / 63 - 31);
        float gx = (float)(rr % 63 - 31);
        h1s[r][t] = silu_f(gy * w1a + gx * w1b + bb1);
    }
    __syncthreads();
    float acc[8] = {0,0,0,0,0,0,0,0};
    for (int k = 0; k < CPB; k++) {
        float w = w2[k * CPB + t];
#pragma unroll
        for (int r = 0; r < 8; r++) acc[r] += h1s[r][k] * w;
    }
    float bb2 = b2[t];
#pragma unroll
    for (int r = 0; r < 8; r++) h2s[r][t] = silu_f(acc[r] + bb2);
    __syncthreads();
    if (t < 64) {
        int r = t >> 3, hh = t & 7;
        float a = b3[hh];
        for (int k = 0; k < CPB; k++) a += h2s[r][k] * w3[k * 8 + hh];
        int rr = rbase + r;
        if (rr < 3969) tab[rr * 8 + hh] = a;
    }
}

__global__ __launch_bounds__(256) void cpb1d_kernel(
    const float* __restrict__ w1, const float* __restrict__ b1,
    const float* __restrict__ w2, const float* __restrict__ b2,
    const float* __restrict__ w3, const float* __restrict__ b3,
    float* __restrict__ tab)
{
    __shared__ float h1s[15][CPB];
    __shared__ float h2s[15][CPB];
    int t = threadIdx.x;
    float w1a = w1[t], bb1 = b1[t];
#pragma unroll
    for (int r = 0; r < 15; r++)
        h1s[r][t] = silu_f((float)(r - 7) * w1a + bb1);
    __syncthreads();
    float acc[15];
#pragma unroll
    for (int r = 0; r < 15; r++) acc[r] = 0.f;
    for (int k = 0; k < CPB; k++) {
        float w = w2[k * CPB + t];
#pragma unroll
        for (int r = 0; r < 15; r++) acc[r] += h1s[r][k] * w;
    }
    float bb2 = b2[t];
#pragma unroll
    for (int r = 0; r < 15; r++) h2s[r][t] = silu_f(acc[r] + bb2);
    __syncthreads();
    if (t < 120) {
        int r = t / 8, hh = t % 8;
        float a = b3[hh];
        for (int k = 0; k < CPB; k++) a += h2s[r][k] * w3[k * 8 + hh];
        tab[r * 8 + hh] = a;
    }
}

// ----------------------------------------------------------------------------
// RMS norm over last dim (512), optional temporal-layout read permutation
// ----------------------------------------------------------------------------
__device__ __forceinline__ long perm_t2s(int t) {
    int f = t & 7;
    int u = t >> 3;                       // b*1024 + hw
    return ((long)((u >> 10) * 8 + f)) * 1024 + (u & 1023);
}

__global__ __launch_bounds__(128) void rmsnorm512_kernel(
    const float* __restrict__ in, float* __restrict__ out,
    const float* __restrict__ gamma, int perm)
{
    int row = blockIdx.x;
    long src = perm ? perm_t2s(row) : (long)row;
    int t = threadIdx.x;
    float4 v = ((const float4*)(in + src * DIM))[t];
    float ss = v.x*v.x + v.y*v.y + v.z*v.z + v.w*v.w;
#pragma unroll
    for (int o = 16; o; o >>= 1) ss += __shfl_xor_sync(0xffffffffu, ss, o);
    __shared__ float red[4];
    if ((t & 31) == 0) red[t >> 5] = ss;
    __syncthreads();
    float tot = red[0] + red[1] + red[2] + red[3];
    float inv = 22.62741699796952f / fmaxf(sqrtf(tot), 1e-12f);   // sqrt(512)
    float4 g = ((const float4*)gamma)[t];
    float4 r;
    r.x = v.x * inv * g.x; r.y = v.y * inv * g.y;
    r.z = v.z * inv * g.z; r.w = v.w * inv * g.w;
    ((float4*)(out + (long)row * DIM))[t] = r;
}

// ----------------------------------------------------------------------------
// Generic SGEMM: C[M,N] = A[M,K] @ B[K,N]; epi: 0 none, 1 +=Res, 2 perm store + Res
// 128x128 tile, 16 K-slab, 8x8 per thread, 256 threads. All dims padded.
// ----------------------------------------------------------------------------
__global__ __launch_bounds__(256) void sgemm_kernel(
    const float* __restrict__ A, const float* __restrict__ B,
    float* __restrict__ C, const float* __restrict__ Res,
    int M, int N, int K, int epi)
{
    __shared__ float As[16][128];
    __shared__ float Bs[16][132];
    int tid = threadIdx.x;
    int bm = blockIdx.y * 128;
    int bn = blockIdx.x * 128;
    int tx = tid & 15, ty = tid >> 4;

    int arow = tid >> 2;            // 0..63
    int acol = (tid & 3) * 4;       // 0,4,8,12
    int brow = tid >> 5;            // 0..7
    int bcol = (tid & 31) * 4;      // 0..124

    float acc[8][8];
#pragma unroll
    for (int i = 0; i < 8; i++)
#pragma unroll
        for (int j = 0; j < 8; j++) acc[i][j] = 0.f;

    for (int k0 = 0; k0 < K; k0 += 16) {
#pragma unroll
        for (int p = 0; p < 2; p++) {
            int r = arow + p * 64;
            float4 v = *(const float4*)(A + (long)(bm + r) * K + k0 + acol);
            As[acol + 0][r] = v.x; As[acol + 1][r] = v.y;
            As[acol + 2][r] = v.z; As[acol + 3][r] = v.w;
        }
#pragma unroll
        for (int p = 0; p < 2; p++) {
            int r = brow + p * 8;
            float4 v = *(const float4*)(B + (long)(k0 + r) * N + bn + bcol);
            *(float4*)&Bs[r][bcol] = v;
        }
        __syncthreads();
#pragma unroll
        for (int kk = 0; kk < 16; kk++) {
            float a[8], b[8];
            *(float4*)(a)     = *(float4*)&As[kk][ty * 8];
            *(float4*)(a + 4) = *(float4*)&As[kk][ty * 8 + 4];
            *(float4*)(b)     = *(float4*)&Bs[kk][tx * 8];
            *(float4*)(b + 4) = *(float4*)&Bs[kk][tx * 8 + 4];
#pragma unroll
            for (int i = 0; i < 8; i++)
#pragma unroll
                for (int j = 0; j < 8; j++) acc[i][j] += a[i] * b[j];
        }
        __syncthreads();
    }

#pragma unroll
    for (int i = 0; i < 8; i++) {
        int m = bm + ty * 8 + i;
        long srow = (epi == 2) ? perm_t2s(m) : (long)m;
        float* crow = C + srow * N + bn + tx * 8;
        float4 c0 = make_float4(acc[i][0], acc[i][1], acc[i][2], acc[i][3]);
        float4 c1 = make_float4(acc[i][4], acc[i][5], acc[i][6], acc[i][7]);
        if (epi != 0) {
            const float* rrow = Res + srow * N + bn + tx * 8;
            float4 r0 = *(const float4*)rrow;
            float4 r1 = *(const float4*)(rrow + 4);
            c0.x += r0.x; c0.y += r0.y; c0.z += r0.z; c0.w += r0.w;
            c1.x += r1.x; c1.y += r1.y; c1.z += r1.z; c1.w += r1.w;
        }
        *(float4*)crow       = c0;
        *(float4*)(crow + 4) = c1;
    }
}

// ----------------------------------------------------------------------------
// Spatial flash attention: 16 seqs x 8 heads, seqlen 1024, dhead 64
// block = 128 queries (one thread per query); key tiles of 32 in smem
// ----------------------------------------------------------------------------
__global__ __launch_bounds__(128) void attn_spatial_kernel(
    const float* __restrict__ q, const float* __restrict__ kv,
    const float* __restrict__ tab, float* __restrict__ o)
{
    __shared__ float ks[32][64];
    __shared__ float vs[32][64];
    int seq = blockIdx.z, h = blockIdx.y;
    int i = blockIdx.x * 128 + threadIdx.x;
    long tok0 = (long)seq * HW;

    float4 qr[16];
    const float4* qp = (const float4*)(q + (tok0 + i) * DIM + h * DHEAD);
#pragma unroll
    for (int c = 0; c < 16; c++) qr[c] = qp[c];

    float4 ov[16];
#pragma unroll
    for (int c = 0; c < 16; c++) ov[c] = make_float4(0.f, 0.f, 0.f, 0.f);
    float mval = -1e30f, l = 0.f;
    int yi = i >> 5, xi = i & 31;

    for (int j0 = 0; j0 < HW; j0 += 32) {
#pragma unroll
        for (int p = 0; p < 4; p++) {
            int qd = threadIdx.x + p * 128;
            int r = qd >> 4, c4 = (qd & 15) * 4;
            *(float4*)&ks[r][c4] = *(const float4*)(kv + (tok0 + j0 + r) * 2 * DIM + h * DHEAD + c4);
            *(float4*)&vs[r][c4] = *(const float4*)(kv + (tok0 + j0 + r) * 2 * DIM + DIM + h * DHEAD + c4);
        }
        __syncthreads();

        float s[32];
        int dyb = (yi - (j0 >> 5) + 31) * 63 + xi + 31;
#pragma unroll
        for (int jj = 0; jj < 32; jj++) {
            const float4* kp = (const float4*)ks[jj];
            float a = 0.f;
#pragma unroll
            for (int c = 0; c < 16; c++) {
                float4 k4 = kp[c];
                a += qr[c].x * k4.x + qr[c].y * k4.y + qr[c].z * k4.z + qr[c].w * k4.w;
            }
            s[jj] = a * SCALE_ATTN + __ldg(&tab[(dyb - jj) * 8 + h]);
        }
        float mt = mval;
#pragma unroll
        for (int jj = 0; jj < 32; jj++) mt = fmaxf(mt, s[jj]);
        float corr = __expf(mval - mt);
        mval = mt;
        l *= corr;
#pragma unroll
        for (int c = 0; c < 16; c++) {
            ov[c].x *= corr; ov[c].y *= corr; ov[c].z *= corr; ov[c].w *= corr;
        }
#pragma unroll
        for (int jj = 0; jj < 32; jj++) {
            float p = __expf(s[jj] - mt);
            l += p;
            const float4* vp = (const float4*)vs[jj];
#pragma unroll
            for (int c = 0; c < 16; c++) {
                float4 v4 = vp[c];
                ov[c].x += p * v4.x; ov[c].y += p * v4.y;
                ov[c].z += p * v4.z; ov[c].w += p * v4.w;
            }
        }
        __syncthreads();
    }
    float inv = 1.f / l;
    float4* op = (float4*)(o + (tok0 + i) * DIM + h * DHEAD);
#pragma unroll
    for (int c = 0; c < 16; c++) {
        ov[c].x *= inv; ov[c].y *= inv; ov[c].z *= inv; ov[c].w *= inv;
        op[c] = ov[c];
    }
}

// ----------------------------------------------------------------------------
// Temporal attention: 2048 seqs, seqlen 8, 8 heads. thread = (head, query).
// ----------------------------------------------------------------------------
__global__ __launch_bounds__(64) void attn_temporal_kernel(
    const float* __restrict__ q, const float* __restrict__ kv,
    const float* __restrict__ tab, float* __restrict__ o)
{
    int seq = blockIdx.x;
    int h = threadIdx.x >> 3, i = threadIdx.x & 7;
    long base = (long)seq * FRAMES;

    float4 qr[16];
    const float4* qp = (const float4*)(q + (base + i) * DIM + h * DHEAD);
#pragma unroll
    for (int c = 0; c < 16; c++) qr[c] = qp[c];

    float s[8];
    float m = -1e30f;
#pragma unroll
    for (int j = 0; j < 8; j++) {
        const float4* kp = (const float4*)(kv + (base + j) * 2 * DIM + h * DHEAD);
        float a = 0.f;
#pragma unroll
        for (int c = 0; c < 16; c++) {
            float4 k4 = kp[c];
            a += qr[c].x * k4.x + qr[c].y * k4.y + qr[c].z * k4.z + qr[c].w * k4.w;
        }
        s[j] = a * SCALE_ATTN + __ldg(&tab[(i - j + 7) * 8 + h]);
        m = fmaxf(m, s[j]);
    }
    float l = 0.f;
#pragma unroll
    for (int j = 0; j < 8; j++) { s[j] = __expf(s[j] - m); l += s[j]; }
    float inv = 1.f / l;

    float4 ov[16];
#pragma unroll
    for (int c = 0; c < 16; c++) ov[c] = make_float4(0.f, 0.f, 0.f, 0.f);
#pragma unroll
    for (int j = 0; j < 8; j++) {
        float p = s[j] * inv;
        const float4* vp = (const float4*)(kv + (base + j) * 2 * DIM + DIM + h * DHEAD);
#pragma unroll
        for (int c = 0; c < 16; c++) {
            float4 v4 = vp[c];
            ov[c].x += p * v4.x; ov[c].y += p * v4.y;
            ov[c].z += p * v4.z; ov[c].w += p * v4.w;
        }
    }
    float4* op = (float4*)(o + (base + i) * DIM + h * DHEAD);
#pragma unroll
    for (int c = 0; c < 16; c++) op[c] = ov[c];
}

// ----------------------------------------------------------------------------
// FF helpers
// ----------------------------------------------------------------------------
__global__ void pad_win_kernel(const float* __restrict__ win, float* __restrict__ wp) {
    int idx = blockIdx.x * 256 + threadIdx.x;           // over 512*2816
    if (idx >= DIM * FF2_P) return;
    int k = idx / FF2_P, n = idx % FF2_P;
    wp[idx] = (n < FF2) ? win[(long)k * FF2 + n] : 0.f;
}

__global__ void pad_wout_kernel(const float* __restrict__ wout, float* __restrict__ wp) {
    int idx = blockIdx.x * 256 + threadIdx.x;           // over 1408*512
    if (idx >= FFI_P * DIM) return;
    int k = idx / DIM, n = idx % DIM;
    wp[idx] = (k < FFI) ? wout[(long)k * DIM + n] : 0.f;
}

__global__ void geglu_kernel(const float* __restrict__ hdn, float* __restrict__ y) {
    int idx = blockIdx.x * 256 + threadIdx.x;           // over 16384*1408
    int m = idx / FFI_P, c = idx % FFI_P;
    float v = 0.f;
    if (c < FFI) {
        float a  = hdn[(long)m * FF2_P + c];
        float gt = hdn[(long)m * FF2_P + FFI + c];
        v = a * (0.5f * gt * (1.f + erff(gt * 0.7071067811865475f)));
    }
    y[(long)m * FFI_P + c] = v;
}

__global__ __launch_bounds__(256) void shiftrms_kernel(
    const float* __restrict__ y, float* __restrict__ yn, const float* __restrict__ g)
{
    __shared__ float buf[FFI];
    __shared__ float red[8];
    int m = blockIdx.x, t = threadIdx.x;
    int f = (m >> 10) & 7;
    float ss = 0.f;
    for (int c = t; c < FFI; c += 256) {
        float v;
        if (c < C1) v = y[(long)m * FFI_P + c];
        else        v = (f > 0) ? y[(long)(m - 1024) * FFI_P + c] : 0.f;
        buf[c] = v;
        ss += v * v;
    }
#pragma unroll
    for (int o = 16; o; o >>= 1) ss += __shfl_xor_sync(0xffffffffu, ss, o);
    if ((t & 31) == 0) red[t >> 5] = ss;
    __syncthreads();
    float tot = 0.f;
#pragma unroll
    for (int w = 0; w < 8; w++) tot += red[w];
    float inv = sqrtf(1365.0f) / fmaxf(sqrtf(tot), 1e-12f);
    for (int c = t; c < FFI_P; c += 256)
        yn[(long)m * FFI_P + c] = (c < FFI) ? buf[c] * inv * g[c] : 0.f;
}

// ----------------------------------------------------------------------------
// Host side
// ----------------------------------------------------------------------------
static float* sym(const void* symbol) {
    void* p = nullptr;
    cudaGetSymbolAddress(&p, symbol);
    return (float*)p;
}

static void launch_sgemm(const float* A, const float* B, float* C, const float* R,
                         int M, int N, int K, int epi) {
    dim3 grid(N / 128, M / 128);
    sgemm_kernel<<<grid, 256>>>(A, B, C, R, M, N, K, epi);
}

extern "C" void kernel_launch(void* const* d_in, const int* in_sizes, int n_in,
                              void* d_out, int out_size) {
    const float* x        = (const float*)d_in[0];
    const float* sa_gamma = (const float*)d_in[1];
    const float* sa_wq    = (const float*)d_in[2];
    const float* sa_wkv   = (const float*)d_in[3];
    const float* sa_wo    = (const float*)d_in[4];
    const float* ta_gamma = (const float*)d_in[5];
    const float* ta_wq    = (const float*)d_in[6];
    const float* ta_wkv   = (const float*)d_in[7];
    const float* ta_wo    = (const float*)d_in[8];
    const float* sp_w1    = (const float*)d_in[9];
    const float* sp_b1    = (const float*)d_in[10];
    const float* sp_w2    = (const float*)d_in[11];
    const float* sp_b2    = (const float*)d_in[12];
    const float* sp_w3    = (const float*)d_in[13];
    const float* sp_b3    = (const float*)d_in[14];
    const float* tp_w1    = (const float*)d_in[15];
    const float* tp_b1    = (const float*)d_in[16];
    const float* tp_w2    = (const float*)d_in[17];
    const float* tp_b2    = (const float*)d_in[18];
    const float* tp_w3    = (const float*)d_in[19];
    const float* tp_b3    = (const float*)d_in[20];
    const float* ff_win   = (const float*)d_in[21];
    const float* ff_gamma = (const float*)d_in[22];
    const float* ff_wout  = (const float*)d_in[23];
    float* out = (float*)d_out;

    float* xs   = sym(g_xs);
    float* xn   = sym(g_xn);
    float* q    = sym(g_q);
    float* kv   = sym(g_kv);
    float* o    = sym(g_o);
    float* res1 = sym(g_res1);
    float* res2 = sym(g_res2);
    float* ffd  = sym(g_ffd);
    float* hdn  = sym(g_hdn);
    float* yb   = sym(g_y);
    float* yn   = sym(g_yn);
    float* wp1  = sym(g_wp1);
    float* wp2  = sym(g_wp2);
    float* sptab = sym(g_sptab);
    float* tptab = sym(g_tptab);

    // bias tables + weight padding (independent of main pipeline order)
    cpb2d_kernel<<<497, 256>>>(sp_w1, sp_b1, sp_w2, sp_b2, sp_w3, sp_b3, sptab);
    cpb1d_kernel<<<1, 256>>>(tp_w1, tp_b1, tp_w2, tp_b2, tp_w3, tp_b3, tptab);
    pad_win_kernel<<<(DIM * FF2_P + 255) / 256, 256>>>(ff_win, wp1);
    pad_wout_kernel<<<(FFI_P * DIM + 255) / 256, 256>>>(ff_wout, wp2);

    // input transpose: (b,c,f,h,w) -> tokens [16384,512]
    transpose_in_kernel<<<dim3(256, 16, 2), dim3(32, 8)>>>(x, xs);

    // ---- spatial attention ----
    rmsnorm512_kernel<<<NTOK, 128>>>(xs, xn, sa_gamma, 0);
    launch_sgemm(xn, sa_wq,  q,  nullptr, NTOK, DIM,     DIM, 0);
    launch_sgemm(xn, sa_wkv, kv, nullptr, NTOK, 2 * DIM, DIM, 0);
    attn_spatial_kernel<<<dim3(8, 8, 16), 128>>>(q, kv, sptab, o);
    launch_sgemm(o, sa_wo, res1, xs, NTOK, DIM, DIM, 1);

    // ---- temporal attention (temporal layout via permuted reads/writes) ----
    rmsnorm512_kernel<<<NTOK, 128>>>(res1, xn, ta_gamma, 1);
    launch_sgemm(xn, ta_wq,  q,  nullptr, NTOK, DIM,     DIM, 0);
    launch_sgemm(xn, ta_wkv, kv, nullptr, NTOK, 2 * DIM, DIM, 0);
    attn_temporal_kernel<<<SEQ_T, 64>>>(q, kv, tptab, o);
    launch_sgemm(o, ta_wo, res2, res1, NTOK, DIM, DIM, 2);   // perm store -> spatial

    // ---- feed forward ----
    launch_sgemm(res2, wp1, hdn, nullptr, NTOK, FF2_P, DIM, 0);
    geglu_kernel<<<(NTOK * FFI_P) / 256, 256>>>(hdn, yb);
    shiftrms_kernel<<<NTOK, 256>>>(yb, yn, ff_gamma);
    launch_sgemm(yn, wp2, ffd, res2, NTOK, DIM, FFI_P, 1);

    // output transpose: tokens -> (b,c,f,h,w)
    transpose_out_kernel<<<dim3(256, 16, 2), dim3(32, 8)>>>(ffd, out);
    (void)in_sizes; (void)n_in; (void)out_size;
}

// round 16
// speedup vs baseline: 1.0011x; 1.0011x over previous
#include <cuda_runtime.h>
#include <cuda_bf16.h>
#include <math.h>

// ----------------------------------------------------------------------------
// Problem constants
// ----------------------------------------------------------------------------
#define BATCH   2
#define DIM     512
#define HEADS   8
#define DHEAD   64
#define FRAMES  8
#define HH      32
#define WW      32
#define HW      1024            // H*W
#define NTOK    16384           // B*F*H*W
#define SEQ_S   16              // B*F spatial sequences
#define SEQ_T   2048            // B*H*W temporal sequences
#define CPB     256
#define FFI     1365            // FF_INNER
#define FFI_P   1408            // padded to mult of 16 (and 128-friendly)
#define FF2     2730            // 2*FF_INNER
#define FF2_P   2816            // padded to mult of 128
#define C1      683             // (FFI+1)//2
#define SCALE_ATTN 0.125f       // 64^-0.5

// ----------------------------------------------------------------------------
// Device scratch (device globals: allocation-free per harness rules)
// ----------------------------------------------------------------------------
__device__ float g_xs  [NTOK * DIM];        // tokens, spatial layout
__device__ float g_xn  [NTOK * DIM];        // rms-normed tokens
__device__ float g_q   [NTOK * DIM];
__device__ float g_kv  [NTOK * 2 * DIM];
__device__ float g_o   [NTOK * DIM];
__device__ float g_res1[NTOK * DIM];        // after spatial attn (spatial layout)
__device__ float g_res2[NTOK * DIM];        // after temporal attn (spatial layout)
__device__ float g_ffd [NTOK * DIM];        // after FF (+res), pre-transpose
__device__ float g_hdn [NTOK * FF2_P];      // FF hidden (padded)
__device__ float g_y   [NTOK * FFI_P];      // geglu output (padded)
__device__ float g_yn  [NTOK * FFI_P];      // shifted + rms-normed (padded)
__device__ float g_wp1 [DIM  * FF2_P];      // padded ff_win
__device__ float g_wp2 [FFI_P * DIM];       // padded ff_wout
__device__ float g_sptab[3969 * 8];
__device__ float g_tptab[15 * 8];

// ----------------------------------------------------------------------------
// Transposes (b: [512][8192] <-> [8192][512])
// ----------------------------------------------------------------------------
__global__ void transpose_in_kernel(const float* __restrict__ x, float* __restrict__ xs) {
    __shared__ float tile[32][33];
    int b  = blockIdx.z;
    int p0 = blockIdx.x * 32;      // fhw
    int c0 = blockIdx.y * 32;      // channel
    int tx = threadIdx.x, ty = threadIdx.y;
    const float* in = x + (long)b * DIM * 8192;
#pragma unroll
    for (int i = 0; i < 32; i += 8)
        tile[ty + i][tx] = in[(long)(c0 + ty + i) * 8192 + p0 + tx];
    __syncthreads();
#pragma unroll
    for (int i = 0; i < 32; i += 8)
        xs[((long)b * 8192 + p0 + ty + i) * DIM + c0 + tx] = tile[tx][ty + i];
}

__global__ void transpose_out_kernel(const float* __restrict__ ffd, float* __restrict__ out) {
    __shared__ float tile[32][33];
    int b  = blockIdx.z;
    int p0 = blockIdx.x * 32;
    int c0 = blockIdx.y * 32;
    int tx = threadIdx.x, ty = threadIdx.y;
#pragma unroll
    for (int i = 0; i < 32; i += 8)
        tile[ty + i][tx] = ffd[((long)b * 8192 + p0 + ty + i) * DIM + c0 + tx];
    __syncthreads();
    float* ob = out + (long)b * DIM * 8192;
#pragma unroll
    for (int i = 0; i < 32; i += 8)
        ob[(long)(c0 + ty + i) * 8192 + p0 + tx] = tile[tx][ty + i];
}

// ----------------------------------------------------------------------------
// CPB bias MLPs
// ----------------------------------------------------------------------------
__device__ __forceinline__ float silu_f(float z) { return z / (1.f + __expf(-z)); }

__global__ __launch_bounds__(256) void cpb2d_kernel(
    const float* __restrict__ w1, const float* __restrict__ b1,
    const float* __restrict__ w2, const float* __restrict__ b2,
    const float* __restrict__ w3, const float* __restrict__ b3,
    float* __restrict__ tab)
{
    __shared__ float h1s[8][CPB];
    __shared__ float h2s[8][CPB];
    int t = threadIdx.x;
    int rbase = blockIdx.x * 8;
    float w1a = w1[t], w1b = w1[CPB + t], bb1 = b1[t];
#pragma unroll
    for (int r = 0; r < 8; r++) {
        int rr = min(rbase + r, 3968);
        float gy = (float)(rr / 63 - 31);
        float gx = (float)(rr % 63 - 31);
        h1s[r][t] = silu_f(gy * w1a + gx * w1b + bb1);
    }
    __syncthreads();
    float acc[8] = {0,0,0,0,0,0,0,0};
    for (int k = 0; k < CPB; k++) {
        float w = w2[k * CPB + t];
#pragma unroll
        for (int r = 0; r < 8; r++) acc[r] += h1s[r][k] * w;
    }
    float bb2 = b2[t];
#pragma unroll
    for (int r = 0; r < 8; r++) h2s[r][t] = silu_f(acc[r] + bb2);
    __syncthreads();
    if (t < 64) {
        int r = t >> 3, hh = t & 7;
        float a = b3[hh];
        for (int k = 0; k < CPB; k++) a += h2s[r][k] * w3[k * 8 + hh];
        int rr = rbase + r;
        if (rr < 3969) tab[rr * 8 + hh] = a;
    }
}

__global__ __launch_bounds__(256) void cpb1d_kernel(
    const float* __restrict__ w1, const float* __restrict__ b1,
    const float* __restrict__ w2, const float* __restrict__ b2,
    const float* __restrict__ w3, const float* __restrict__ b3,
    float* __restrict__ tab)
{
    __shared__ float h1s[15][CPB];
    __shared__ float h2s[15][CPB];
    int t = threadIdx.x;
    float w1a = w1[t], bb1 = b1[t];
#pragma unroll
    for (int r = 0; r < 15; r++)
        h1s[r][t] = silu_f((float)(r - 7) * w1a + bb1);
    __syncthreads();
    float acc[15];
#pragma unroll
    for (int r = 0; r < 15; r++) acc[r] = 0.f;
    for (int k = 0; k < CPB; k++) {
        float w = w2[k * CPB + t];
#pragma unroll
        for (int r = 0; r < 15; r++) acc[r] += h1s[r][k] * w;
    }
    float bb2 = b2[t];
#pragma unroll
    for (int r = 0; r < 15; r++) h2s[r][t] = silu_f(acc[r] + bb2);
    __syncthreads();
    if (t < 120) {
        int r = t / 8, hh = t % 8;
        float a = b3[hh];
        for (int k = 0; k < CPB; k++) a += h2s[r][k] * w3[k * 8 + hh];
        tab[r * 8 + hh] = a;
    }
}

// ----------------------------------------------------------------------------
// RMS norm over last dim (512), optional temporal-layout read permutation
// ----------------------------------------------------------------------------
__device__ __forceinline__ long perm_t2s(int t) {
    int f = t & 7;
    int u = t >> 3;                       // b*1024 + hw
    return ((long)((u >> 10) * 8 + f)) * 1024 + (u & 1023);
}

__global__ __launch_bounds__(128) void rmsnorm512_kernel(
    const float* __restrict__ in, float* __restrict__ out,
    const float* __restrict__ gamma, int perm)
{
    int row = blockIdx.x;
    long src = perm ? perm_t2s(row) : (long)row;
    int t = threadIdx.x;
    float4 v = ((const float4*)(in + src * DIM))[t];
    float ss = v.x*v.x + v.y*v.y + v.z*v.z + v.w*v.w;
#pragma unroll
    for (int o = 16; o; o >>= 1) ss += __shfl_xor_sync(0xffffffffu, ss, o);
    __shared__ float red[4];
    if ((t & 31) == 0) red[t >> 5] = ss;
    __syncthreads();
    float tot = red[0] + red[1] + red[2] + red[3];
    float inv = 22.62741699796952f / fmaxf(sqrtf(tot), 1e-12f);   // sqrt(512)
    float4 g = ((const float4*)gamma)[t];
    float4 r;
    r.x = v.x * inv * g.x; r.y = v.y * inv * g.y;
    r.z = v.z * inv * g.z; r.w = v.w * inv * g.w;
    ((float4*)(out + (long)row * DIM))[t] = r;
}

// ----------------------------------------------------------------------------
// Generic SGEMM: C[M,N] = A[M,K] @ B[K,N]; epi: 0 none, 1 +=Res, 2 perm store + Res
// 128x128 tile, 16 K-slab, 8x8 per thread, 256 threads. All dims padded.
// ----------------------------------------------------------------------------
__global__ __launch_bounds__(256) void sgemm_kernel(
    const float* __restrict__ A, const float* __restrict__ B,
    float* __restrict__ C, const float* __restrict__ Res,
    int M, int N, int K, int epi)
{
    __shared__ float As[16][128];
    __shared__ float Bs[16][132];
    int tid = threadIdx.x;
    int bm = blockIdx.y * 128;
    int bn = blockIdx.x * 128;
    int tx = tid & 15, ty = tid >> 4;

    int arow = tid >> 2;            // 0..63
    int acol = (tid & 3) * 4;       // 0,4,8,12
    int brow = tid >> 5;            // 0..7
    int bcol = (tid & 31) * 4;      // 0..124

    float acc[8][8];
#pragma unroll
    for (int i = 0; i < 8; i++)
#pragma unroll
        for (int j = 0; j < 8; j++) acc[i][j] = 0.f;

    for (int k0 = 0; k0 < K; k0 += 16) {
#pragma unroll
        for (int p = 0; p < 2; p++) {
            int r = arow + p * 64;
            float4 v = *(const float4*)(A + (long)(bm + r) * K + k0 + acol);
            As[acol + 0][r] = v.x; As[acol + 1][r] = v.y;
            As[acol + 2][r] = v.z; As[acol + 3][r] = v.w;
        }
#pragma unroll
        for (int p = 0; p < 2; p++) {
            int r = brow + p * 8;
            float4 v = *(const float4*)(B + (long)(k0 + r) * N + bn + bcol);
            *(float4*)&Bs[r][bcol] = v;
        }
        __syncthreads();
#pragma unroll
        for (int kk = 0; kk < 16; kk++) {
            float a[8], b[8];
            *(float4*)(a)     = *(float4*)&As[kk][ty * 8];
            *(float4*)(a + 4) = *(float4*)&As[kk][ty * 8 + 4];
            *(float4*)(b)     = *(float4*)&Bs[kk][tx * 8];
            *(float4*)(b + 4) = *(float4*)&Bs[kk][tx * 8 + 4];
#pragma unroll
            for (int i = 0; i < 8; i++)
#pragma unroll
                for (int j = 0; j < 8; j++) acc[i][j] += a[i] * b[j];
        }
        __syncthreads();
    }

#pragma unroll
    for (int i = 0; i < 8; i++) {
        int m = bm + ty * 8 + i;
        long srow = (epi == 2) ? perm_t2s(m) : (long)m;
        float* crow = C + srow * N + bn + tx * 8;
        float4 c0 = make_float4(acc[i][0], acc[i][1], acc[i][2], acc[i][3]);
        float4 c1 = make_float4(acc[i][4], acc[i][5], acc[i][6], acc[i][7]);
        if (epi != 0) {
            const float* rrow = Res + srow * N + bn + tx * 8;
            float4 r0 = *(const float4*)rrow;
            float4 r1 = *(const float4*)(rrow + 4);
            c0.x += r0.x; c0.y += r0.y; c0.z += r0.z; c0.w += r0.w;
            c1.x += r1.x; c1.y += r1.y; c1.z += r1.z; c1.w += r1.w;
        }
        *(float4*)crow       = c0;
        *(float4*)(crow + 4) = c1;
    }
}

// ----------------------------------------------------------------------------
// Spatial flash attention: 16 seqs x 8 heads, seqlen 1024, dhead 64
// block = 128 queries (one thread per query); key tiles of 32 in smem
// ----------------------------------------------------------------------------
__global__ __launch_bounds__(128) void attn_spatial_kernel(
    const float* __restrict__ q, const float* __restrict__ kv,
    const float* __restrict__ tab, float* __restrict__ o)
{
    __shared__ float ks[32][64];
    __shared__ float vs[32][64];
    int seq = blockIdx.z, h = blockIdx.y;
    int i = blockIdx.x * 128 + threadIdx.x;
    long tok0 = (long)seq * HW;

    float4 qr[16];
    const float4* qp = (const float4*)(q + (tok0 + i) * DIM + h * DHEAD);
#pragma unroll
    for (int c = 0; c < 16; c++) qr[c] = qp[c];

    float4 ov[16];
#pragma unroll
    for (int c = 0; c < 16; c++) ov[c] = make_float4(0.f, 0.f, 0.f, 0.f);
    float mval = -1e30f, l = 0.f;
    int yi = i >> 5, xi = i & 31;

    for (int j0 = 0; j0 < HW; j0 += 32) {
#pragma unroll
        for (int p = 0; p < 4; p++) {
            int qd = threadIdx.x + p * 128;
            int r = qd >> 4, c4 = (qd & 15) * 4;
            *(float4*)&ks[r][c4] = *(const float4*)(kv + (tok0 + j0 + r) * 2 * DIM + h * DHEAD + c4);
            *(float4*)&vs[r][c4] = *(const float4*)(kv + (tok0 + j0 + r) * 2 * DIM + DIM + h * DHEAD + c4);
        }
        __syncthreads();

        float s[32];
        int dyb = (yi - (j0 >> 5) + 31) * 63 + xi + 31;
#pragma unroll
        for (int jj = 0; jj < 32; jj++) {
            const float4* kp = (const float4*)ks[jj];
            float a = 0.f;
#pragma unroll
            for (int c = 0; c < 16; c++) {
                float4 k4 = kp[c];
                a += qr[c].x * k4.x + qr[c].y * k4.y + qr[c].z * k4.z + qr[c].w * k4.w;
            }
            s[jj] = a * SCALE_ATTN + __ldg(&tab[(dyb - jj) * 8 + h]);
        }
        float mt = mval;
#pragma unroll
        for (int jj = 0; jj < 32; jj++) mt = fmaxf(mt, s[jj]);
        float corr = __expf(mval - mt);
        mval = mt;
        l *= corr;
#pragma unroll
        for (int c = 0; c < 16; c++) {
            ov[c].x *= corr; ov[c].y *= corr; ov[c].z *= corr; ov[c].w *= corr;
        }
#pragma unroll
        for (int jj = 0; jj < 32; jj++) {
            float p = __expf(s[jj] - mt);
            l += p;
            const float4* vp = (const float4*)vs[jj];
#pragma unroll
            for (int c = 0; c < 16; c++) {
                float4 v4 = vp[c];
                ov[c].x += p * v4.x; ov[c].y += p * v4.y;
                ov[c].z += p * v4.z; ov[c].w += p * v4.w;
            }
        }
        __syncthreads();
    }
    float inv = 1.f / l;
    float4* op = (float4*)(o + (tok0 + i) * DIM + h * DHEAD);
#pragma unroll
    for (int c = 0; c < 16; c++) {
        ov[c].x *= inv; ov[c].y *= inv; ov[c].z *= inv; ov[c].w *= inv;
        op[c] = ov[c];
    }
}

// ----------------------------------------------------------------------------
// Temporal attention: 2048 seqs, seqlen 8, 8 heads. thread = (head, query).
// ----------------------------------------------------------------------------
__global__ __launch_bounds__(64) void attn_temporal_kernel(
    const float* __restrict__ q, const float* __restrict__ kv,
    const float* __restrict__ tab, float* __restrict__ o)
{
    int seq = blockIdx.x;
    int h = threadIdx.x >> 3, i = threadIdx.x & 7;
    long base = (long)seq * FRAMES;

    float4 qr[16];
    const float4* qp = (const float4*)(q + (base + i) * DIM + h * DHEAD);
#pragma unroll
    for (int c = 0; c < 16; c++) qr[c] = qp[c];

    float s[8];
    float m = -1e30f;
#pragma unroll
    for (int j = 0; j < 8; j++) {
        const float4* kp = (const float4*)(kv + (base + j) * 2 * DIM + h * DHEAD);
        float a = 0.f;
#pragma unroll
        for (int c = 0; c < 16; c++) {
            float4 k4 = kp[c];
            a += qr[c].x * k4.x + qr[c].y * k4.y + qr[c].z * k4.z + qr[c].w * k4.w;
        }
        s[j] = a * SCALE_ATTN + __ldg(&tab[(i - j + 7) * 8 + h]);
        m = fmaxf(m, s[j]);
    }
    float l = 0.f;
#pragma unroll
    for (int j = 0; j < 8; j++) { s[j] = __expf(s[j] - m); l += s[j]; }
    float inv = 1.f / l;

    float4 ov[16];
#pragma unroll
    for (int c = 0; c < 16; c++) ov[c] = make_float4(0.f, 0.f, 0.f, 0.f);
#pragma unroll
    for (int j = 0; j < 8; j++) {
        float p = s[j] * inv;
        const float4* vp = (const float4*)(kv + (base + j) * 2 * DIM + DIM + h * DHEAD);
#pragma unroll
        for (int c = 0; c < 16; c++) {
            float4 v4 = vp[c];
            ov[c].x += p * v4.x; ov[c].y += p * v4.y;
            ov[c].z += p * v4.z; ov[c].w += p * v4.w;
        }
    }
    float4* op = (float4*)(o + (base + i) * DIM + h * DHEAD);
#pragma unroll
    for (int c = 0; c < 16; c++) op[c] = ov[c];
}

// ----------------------------------------------------------------------------
// FF helpers
// ----------------------------------------------------------------------------
__global__ void pad_win_kernel(const float* __restrict__ win, float* __restrict__ wp) {
    int idx = blockIdx.x * 256 + threadIdx.x;           // over 512*2816
    if (idx >= DIM * FF2_P) return;
    int k = idx / FF2_P, n = idx % FF2_P;
    wp[idx] = (n < FF2) ? win[(long)k * FF2 + n] : 0.f;
}

__global__ void pad_wout_kernel(const float* __restrict__ wout, float* __restrict__ wp) {
    int idx = blockIdx.x * 256 + threadIdx.x;           // over 1408*512
    if (idx >= FFI_P * DIM) return;
    int k = idx / DIM, n = idx % DIM;
    wp[idx] = (k < FFI) ? wout[(long)k * DIM + n] : 0.f;
}

__global__ void geglu_kernel(const float* __restrict__ hdn, float* __restrict__ y) {
    int idx = blockIdx.x * 256 + threadIdx.x;           // over 16384*1408
    int m = idx / FFI_P, c = idx % FFI_P;
    float v = 0.f;
    if (c < FFI) {
        float a  = hdn[(long)m * FF2_P + c];
        float gt = hdn[(long)m * FF2_P + FFI + c];
        v = a * (0.5f * gt * (1.f + erff(gt * 0.7071067811865475f)));
    }
    y[(long)m * FFI_P + c] = v;
}

__global__ __launch_bounds__(256) void shiftrms_kernel(
    const float* __restrict__ y, float* __restrict__ yn, const float* __restrict__ g)
{
    __shared__ float buf[FFI];
    __shared__ float red[8];
    int m = blockIdx.x, t = threadIdx.x;
    int f = (m >> 10) & 7;
    float ss = 0.f;
    for (int c = t; c < FFI; c += 256) {
        float v;
        if (c < C1) v = y[(long)m * FFI_P + c];
        else        v = (f > 0) ? y[(long)(m - 1024) * FFI_P + c] : 0.f;
        buf[c] = v;
        ss += v * v;
    }
#pragma unroll
    for (int o = 16; o; o >>= 1) ss += __shfl_xor_sync(0xffffffffu, ss, o);
    if ((t & 31) == 0) red[t >> 5] = ss;
    __syncthreads();
    float tot = 0.f;
#pragma unroll
    for (int w = 0; w < 8; w++) tot += red[w];
    float inv = sqrtf(1365.0f) / fmaxf(sqrtf(tot), 1e-12f);
    for (int c = t; c < FFI_P; c += 256)
        yn[(long)m * FFI_P + c] = (c < FFI) ? buf[c] * inv * g[c] : 0.f;
}

// ----------------------------------------------------------------------------
// Host side
// ----------------------------------------------------------------------------
static float* sym(const void* symbol) {
    void* p = nullptr;
    cudaGetSymbolAddress(&p, symbol);
    return (float*)p;
}

static void launch_sgemm(const float* A, const float* B, float* C, const float* R,
                         int M, int N, int K, int epi) {
    dim3 grid(N / 128, M / 128);
    sgemm_kernel<<<grid, 256>>>(A, B, C, R, M, N, K, epi);
}

extern "C" void kernel_launch(void* const* d_in, const int* in_sizes, int n_in,
                              void* d_out, int out_size) {
    const float* x        = (const float*)d_in[0];
    const float* sa_gamma = (const float*)d_in[1];
    const float* sa_wq    = (const float*)d_in[2];
    const float* sa_wkv   = (const float*)d_in[3];
    const float* sa_wo    = (const float*)d_in[4];
    const float* ta_gamma = (const float*)d_in[5];
    const float* ta_wq    = (const float*)d_in[6];
    const float* ta_wkv   = (const float*)d_in[7];
    const float* ta_wo    = (const float*)d_in[8];
    const float* sp_w1    = (const float*)d_in[9];
    const float* sp_b1    = (const float*)d_in[10];
    const float* sp_w2    = (const float*)d_in[11];
    const float* sp_b2    = (const float*)d_in[12];
    const float* sp_w3    = (const float*)d_in[13];
    const float* sp_b3    = (const float*)d_in[14];
    const float* tp_w1    = (const float*)d_in[15];
    const float* tp_b1    = (const float*)d_in[16];
    const float* tp_w2    = (const float*)d_in[17];
    const float* tp_b2    = (const float*)d_in[18];
    const float* tp_w3    = (const float*)d_in[19];
    const float* tp_b3    = (const float*)d_in[20];
    const float* ff_win   = (const float*)d_in[21];
    const float* ff_gamma = (const float*)d_in[22];
    const float* ff_wout  = (const float*)d_in[23];
    float* out = (float*)d_out;

    float* xs   = sym(g_xs);
    float* xn   = sym(g_xn);
    float* q    = sym(g_q);
    float* kv   = sym(g_kv);
    float* o    = sym(g_o);
    float* res1 = sym(g_res1);
    float* res2 = sym(g_res2);
    float* ffd  = sym(g_ffd);
    float* hdn  = sym(g_hdn);
    float* yb   = sym(g_y);
    float* yn   = sym(g_yn);
    float* wp1  = sym(g_wp1);
    float* wp2  = sym(g_wp2);
    float* sptab = sym(g_sptab);
    float* tptab = sym(g_tptab);

    // bias tables + weight padding (independent of main pipeline order)
    cpb2d_kernel<<<497, 256>>>(sp_w1, sp_b1, sp_w2, sp_b2, sp_w3, sp_b3, sptab);
    cpb1d_kernel<<<1, 256>>>(tp_w1, tp_b1, tp_w2, tp_b2, tp_w3, tp_b3, tptab);
    pad_win_kernel<<<(DIM * FF2_P + 255) / 256, 256>>>(ff_win, wp1);
    pad_wout_kernel<<<(FFI_P * DIM + 255) / 256, 256>>>(ff_wout, wp2);

    // input transpose: (b,c,f,h,w) -> tokens [16384,512]
    transpose_in_kernel<<<dim3(256, 16, 2), dim3(32, 8)>>>(x, xs);

    // ---- spatial attention ----
    rmsnorm512_kernel<<<NTOK, 128>>>(xs, xn, sa_gamma, 0);
    launch_sgemm(xn, sa_wq,  q,  nullptr, NTOK, DIM,     DIM, 0);
    launch_sgemm(xn, sa_wkv, kv, nullptr, NTOK, 2 * DIM, DIM, 0);
    attn_spatial_kernel<<<dim3(8, 8, 16), 128>>>(q, kv, sptab, o);
    launch_sgemm(o, sa_wo, res1, xs, NTOK, DIM, DIM, 1);

    // ---- temporal attention (temporal layout via permuted reads/writes) ----
    rmsnorm512_kernel<<<NTOK, 128>>>(res1, xn, ta_gamma, 1);
    launch_sgemm(xn, ta_wq,  q,  nullptr, NTOK, DIM,     DIM, 0);
    launch_sgemm(xn, ta_wkv, kv, nullptr, NTOK, 2 * DIM, DIM, 0);
    attn_temporal_kernel<<<SEQ_T, 64>>>(q, kv, tptab, o);
    launch_sgemm(o, ta_wo, res2, res1, NTOK, DIM, DIM, 2);   // perm store -> spatial

    // ---- feed forward ----
    launch_sgemm(res2, wp1, hdn, nullptr, NTOK, FF2_P, DIM, 0);
    geglu_kernel<<<(NTOK * FFI_P) / 256, 256>>>(hdn, yb);
    shiftrms_kernel<<<NTOK, 256>>>(yb, yn, ff_gamma);
    launch_sgemm(yn, wp2, ffd, res2, NTOK, DIM, FFI_P, 1);

    // output transpose: tokens -> (b,c,f,h,w)
    transpose_out_kernel<<<dim3(256, 16, 2), dim3(32, 8)>>>(ffd, out);
    (void)in_sizes; (void)n_in; (void)out_size;
}

// round 17
// speedup vs baseline: 2.3274x; 2.3248x over previous
#include <cuda_runtime.h>
#include <cuda_fp16.h>
#include <cuda_bf16.h>
#include <math.h>

// ----------------------------------------------------------------------------
// Problem constants
// ----------------------------------------------------------------------------
#define BATCH   2
#define DIM     512
#define HEADS   8
#define DHEAD   64
#define FRAMES  8
#define HW      1024
#define NTOK    16384
#define SEQ_T   2048
#define CPB     256
#define FFI     1365
#define FFI_P   1408
#define FF2     2730
#define FF2_P   2816
#define C1      683
#define SCALE_ATTN 0.125f

// ----------------------------------------------------------------------------
// Device scratch
// ----------------------------------------------------------------------------
__device__ float  g_xs   [NTOK * DIM];
__device__ __half g_xnh  [NTOK * DIM];
__device__ float  g_q    [NTOK * DIM];
__device__ float  g_kv   [NTOK * 2 * DIM];
__device__ __half g_oh   [NTOK * DIM];
__device__ float  g_res1 [NTOK * DIM];
__device__ float  g_res2 [NTOK * DIM];
__device__ __half g_res2h[NTOK * DIM];
__device__ float  g_ffd  [NTOK * DIM];
__device__ float  g_hdn  [NTOK * FF2_P];
__device__ float  g_y    [NTOK * FFI_P];
__device__ __half g_ynh  [NTOK * FFI_P];
__device__ float  g_sptab[3969 * 8];
__device__ float  g_tptab[15 * 8];
// transposed fp16 weights [N][K]
__device__ __half g_wt_saq  [DIM * DIM];
__device__ __half g_wt_sakv [2 * DIM * DIM];
__device__ __half g_wt_sao  [DIM * DIM];
__device__ __half g_wt_taq  [DIM * DIM];
__device__ __half g_wt_takv [2 * DIM * DIM];
__device__ __half g_wt_tao  [DIM * DIM];
__device__ __half g_wt_ffin [FF2_P * DIM];
__device__ __half g_wt_ffout[DIM * FFI_P];

// ----------------------------------------------------------------------------
// Transposes (b: [512][8192] <-> [8192][512])
// ----------------------------------------------------------------------------
__global__ void transpose_in_kernel(const float* __restrict__ x, float* __restrict__ xs) {
    __shared__ float tile[32][33];
    int b  = blockIdx.z;
    int p0 = blockIdx.x * 32;
    int c0 = blockIdx.y * 32;
    int tx = threadIdx.x, ty = threadIdx.y;
    const float* in = x + (long)b * DIM * 8192;
#pragma unroll
    for (int i = 0; i < 32; i += 8)
        tile[ty + i][tx] = in[(long)(c0 + ty + i) * 8192 + p0 + tx];
    __syncthreads();
#pragma unroll
    for (int i = 0; i < 32; i += 8)
        xs[((long)b * 8192 + p0 + ty + i) * DIM + c0 + tx] = tile[tx][ty + i];
}

__global__ void transpose_out_kernel(const float* __restrict__ ffd, float* __restrict__ out) {
    __shared__ float tile[32][33];
    int b  = blockIdx.z;
    int p0 = blockIdx.x * 32;
    int c0 = blockIdx.y * 32;
    int tx = threadIdx.x, ty = threadIdx.y;
#pragma unroll
    for (int i = 0; i < 32; i += 8)
        tile[ty + i][tx] = ffd[((long)b * 8192 + p0 + ty + i) * DIM + c0 + tx];
    __syncthreads();
    float* ob = out + (long)b * DIM * 8192;
#pragma unroll
    for (int i = 0; i < 32; i += 8)
        ob[(long)(c0 + ty + i) * 8192 + p0 + tx] = tile[tx][ty + i];
}

// ----------------------------------------------------------------------------
// Weight transpose + fp16 convert: W[K,N] fp32 -> Wt[Np,Kp] half (zero-padded)
// ----------------------------------------------------------------------------
__global__ void wconv_kernel(const float* __restrict__ W, __half* __restrict__ Wt,
                             int K, int N, int Kp, int Np) {
    __shared__ float tile[32][33];
    int k0 = blockIdx.x * 32, n0 = blockIdx.y * 32;
    int tx = threadIdx.x, ty = threadIdx.y;
#pragma unroll
    for (int i = 0; i < 32; i += 8) {
        int k = k0 + ty + i, n = n0 + tx;
        tile[ty + i][tx] = (k < K && n < N) ? W[(long)k * N + n] : 0.f;
    }
    __syncthreads();
#pragma unroll
    for (int i = 0; i < 32; i += 8) {
        int n = n0 + ty + i, k = k0 + tx;
        if (n < Np && k < Kp)
            Wt[(long)n * Kp + k] = __float2half(tile[tx][ty + i]);
    }
}

// ----------------------------------------------------------------------------
// CPB bias MLPs
// ----------------------------------------------------------------------------
__device__ __forceinline__ float silu_f(float z) { return z / (1.f + __expf(-z)); }

__global__ __launch_bounds__(256) void cpb2d_kernel(
    const float* __restrict__ w1, const float* __restrict__ b1,
    const float* __restrict__ w2, const float* __restrict__ b2,
    const float* __restrict__ w3, const float* __restrict__ b3,
    float* __restrict__ tab)
{
    __shared__ float h1s[8][CPB];
    __shared__ float h2s[8][CPB];
    int t = threadIdx.x;
    int rbase = blockIdx.x * 8;
    float w1a = w1[t], w1b = w1[CPB + t], bb1 = b1[t];
#pragma unroll
    for (int r = 0; r < 8; r++) {
        int rr = min(rbase + r, 3968);
        float gy = (float)(rr / 63 - 31);
        float gx = (float)(rr % 63 - 31);
        h1s[r][t] = silu_f(gy * w1a + gx * w1b + bb1);
    }
    __syncthreads();
    float acc[8] = {0,0,0,0,0,0,0,0};
    for (int k = 0; k < CPB; k++) {
        float w = w2[k * CPB + t];
#pragma unroll
        for (int r = 0; r < 8; r++) acc[r] += h1s[r][k] * w;
    }
    float bb2 = b2[t];
#pragma unroll
    for (int r = 0; r < 8; r++) h2s[r][t] = silu_f(acc[r] + bb2);
    __syncthreads();
    if (t < 64) {
        int r = t >> 3, hh = t & 7;
        float a = b3[hh];
        for (int k = 0; k < CPB; k++) a += h2s[r][k] * w3[k * 8 + hh];
        int rr = rbase + r;
        if (rr < 3969) tab[rr * 8 + hh] = a;
    }
}

__global__ __launch_bounds__(256) void cpb1d_kernel(
    const float* __restrict__ w1, const float* __restrict__ b1,
    const float* __restrict__ w2, const float* __restrict__ b2,
    const float* __restrict__ w3, const float* __restrict__ b3,
    float* __restrict__ tab)
{
    __shared__ float h1s[15][CPB];
    __shared__ float h2s[15][CPB];
    int t = threadIdx.x;
    float w1a = w1[t], bb1 = b1[t];
#pragma unroll
    for (int r = 0; r < 15; r++)
        h1s[r][t] = silu_f((float)(r - 7) * w1a + bb1);
    __syncthreads();
    float acc[15];
#pragma unroll
    for (int r = 0; r < 15; r++) acc[r] = 0.f;
    for (int k = 0; k < CPB; k++) {
        float w = w2[k * CPB + t];
#pragma unroll
        for (int r = 0; r < 15; r++) acc[r] += h1s[r][k] * w;
    }
    float bb2 = b2[t];
#pragma unroll
    for (int r = 0; r < 15; r++) h2s[r][t] = silu_f(acc[r] + bb2);
    __syncthreads();
    if (t < 120) {
        int r = t / 8, hh = t % 8;
        float a = b3[hh];
        for (int k = 0; k < CPB; k++) a += h2s[r][k] * w3[k * 8 + hh];
        tab[r * 8 + hh] = a;
    }
}

// ----------------------------------------------------------------------------
// RMS norm over last dim (512) -> fp16, optional temporal-layout read perm
// ----------------------------------------------------------------------------
__device__ __forceinline__ long perm_t2s(int t) {
    int f = t & 7;
    int u = t >> 3;
    return ((long)((u >> 10) * 8 + f)) * 1024 + (u & 1023);
}

__global__ __launch_bounds__(128) void rmsnorm512_kernel(
    const float* __restrict__ in, __half* __restrict__ out,
    const float* __restrict__ gamma, int perm)
{
    int row = blockIdx.x;
    long src = perm ? perm_t2s(row) : (long)row;
    int t = threadIdx.x;
    float4 v = ((const float4*)(in + src * DIM))[t];
    float ss = v.x*v.x + v.y*v.y + v.z*v.z + v.w*v.w;
#pragma unroll
    for (int o = 16; o; o >>= 1) ss += __shfl_xor_sync(0xffffffffu, ss, o);
    __shared__ float red[4];
    if ((t & 31) == 0) red[t >> 5] = ss;
    __syncthreads();
    float tot = red[0] + red[1] + red[2] + red[3];
    float inv = 22.62741699796952f / fmaxf(sqrtf(tot), 1e-12f);
    float4 g = ((const float4*)gamma)[t];
    __half2* op = (__half2*)(out + (long)row * DIM);
    op[t * 2]     = __floats2half2_rn(v.x * inv * g.x, v.y * inv * g.y);
    op[t * 2 + 1] = __floats2half2_rn(v.z * inv * g.z, v.w * inv * g.w);
}

// ----------------------------------------------------------------------------
// fp16 tensor-core GEMM: C[M,N] = A[M,K](half) @ Bt[N,K](half)^T
// flags: bit0 = +Res, bit1 = perm store row, bit2 = dual half output Ch
// BM=128 BN=64 BK=64, 256 threads (8 warps, 4x2), warp tile 32x32
// ----------------------------------------------------------------------------
__device__ __forceinline__ void mma16816(float* d, const unsigned* a, const unsigned* b) {
    asm volatile(
        "mma.sync.aligned.m16n8k16.row.col.f32.f16.f16.f32 "
        "{%0,%1,%2,%3}, {%4,%5,%6,%7}, {%8,%9}, {%0,%1,%2,%3};\n"
        : "+f"(d[0]), "+f"(d[1]), "+f"(d[2]), "+f"(d[3])
        : "r"(a[0]), "r"(a[1]), "r"(a[2]), "r"(a[3]), "r"(b[0]), "r"(b[1]));
}
__device__ __forceinline__ void ldsm4(unsigned* r, const __half* p) {
    unsigned addr = (unsigned)__cvta_generic_to_shared(p);
    asm volatile("ldmatrix.sync.aligned.m8n8.x4.shared.b16 {%0,%1,%2,%3}, [%4];\n"
        : "=r"(r[0]), "=r"(r[1]), "=r"(r[2]), "=r"(r[3]) : "r"(addr));
}
__device__ __forceinline__ void cpasync16(__half* dst, const __half* src) {
    unsigned d = (unsigned)__cvta_generic_to_shared(dst);
    asm volatile("cp.async.cg.shared.global [%0], [%1], 16;\n" :: "r"(d), "l"(src));
}

__device__ __forceinline__ void hload_stage(
    const __half* __restrict__ A, const __half* __restrict__ Bt,
    __half* as, __half* bs, int bm, int bn, int K, int k0, int tid)
{
#pragma unroll
    for (int p = 0; p < 4; p++) {
        int c = tid + p * 256;
        int row = c >> 3, ch = c & 7;
        cpasync16(as + row * 64 + ((ch ^ (row & 7)) << 3),
                  A + (long)(bm + row) * K + k0 + (ch << 3));
    }
#pragma unroll
    for (int p = 0; p < 2; p++) {
        int c = tid + p * 256;
        int row = c >> 3, ch = c & 7;
        cpasync16(bs + row * 64 + ((ch ^ (row & 7)) << 3),
                  Bt + (long)(bn + row) * K + k0 + (ch << 3));
    }
}

__global__ __launch_bounds__(256) void hgemm_kernel(
    const __half* __restrict__ A, const __half* __restrict__ Bt,
    float* __restrict__ C, const float* __restrict__ Res, __half* __restrict__ Ch,
    int M, int N, int K, int flags)
{
    __shared__ __half As[2][128 * 64];
    __shared__ __half Bs[2][64 * 64];
    int tid = threadIdx.x;
    int lane = tid & 31;
    int wid = tid >> 5;
    int wm = wid >> 1, wn = wid & 1;
    int bm = blockIdx.y * 128, bn = blockIdx.x * 64;

    float acc[2][4][4];
#pragma unroll
    for (int i = 0; i < 2; i++)
#pragma unroll
        for (int j = 0; j < 4; j++)
#pragma unroll
            for (int r = 0; r < 4; r++) acc[i][j][r] = 0.f;

    const int ksteps = K >> 6;
    hload_stage(A, Bt, As[0], Bs[0], bm, bn, K, 0, tid);
    asm volatile("cp.async.commit_group;\n");

    for (int s = 0; s < ksteps; s++) {
        asm volatile("cp.async.wait_group 0;\n");
        __syncthreads();
        if (s + 1 < ksteps) {
            hload_stage(A, Bt, As[(s + 1) & 1], Bs[(s + 1) & 1], bm, bn, K, (s + 1) << 6, tid);
            asm volatile("cp.async.commit_group;\n");
        }
        const __half* as = As[s & 1];
        const __half* bs = Bs[s & 1];
#pragma unroll
        for (int kk = 0; kk < 64; kk += 16) {
            unsigned a[2][4], b[4][2];
#pragma unroll
            for (int mt = 0; mt < 2; mt++) {
                int r = wm * 32 + mt * 16 + (lane & 15);
                int ch = (kk >> 3) + (lane >> 4);
                ldsm4(a[mt], as + r * 64 + ((ch ^ (r & 7)) << 3));
            }
#pragma unroll
            for (int np = 0; np < 2; np++) {
                int mat = lane >> 3;
                int n = wn * 32 + np * 16 + ((mat >> 1) << 3) + (lane & 7);
                int ch = (kk >> 3) + (mat & 1);
                unsigned t4[4];
                ldsm4(t4, bs + n * 64 + ((ch ^ (n & 7)) << 3));
                b[np * 2][0] = t4[0]; b[np * 2][1] = t4[1];
                b[np * 2 + 1][0] = t4[2]; b[np * 2 + 1][1] = t4[3];
            }
#pragma unroll
            for (int mt = 0; mt < 2; mt++)
#pragma unroll
                for (int nt = 0; nt < 4; nt++)
                    mma16816(acc[mt][nt], a[mt], b[nt]);
        }
        __syncthreads();
    }

#pragma unroll
    for (int mt = 0; mt < 2; mt++)
#pragma unroll
        for (int nt = 0; nt < 4; nt++) {
            int mA = bm + wm * 32 + mt * 16 + (lane >> 2);
            int n  = bn + wn * 32 + nt * 8 + ((lane & 3) << 1);
#pragma unroll
            for (int h = 0; h < 2; h++) {
                int m = mA + h * 8;
                float2 v;
                v.x = acc[mt][nt][h * 2];
                v.y = acc[mt][nt][h * 2 + 1];
                long sr = (flags & 2) ? perm_t2s(m) : (long)m;
                if (flags & 1) {
                    float2 r = *(const float2*)(Res + sr * N + n);
                    v.x += r.x; v.y += r.y;
                }
                *(float2*)(C + sr * N + n) = v;
                if (flags & 4)
                    *(__half2*)(Ch + sr * N + n) = __floats2half2_rn(v.x, v.y);
            }
        }
}

// ----------------------------------------------------------------------------
// Spatial flash attention: fp32 math, fp16 output
// ----------------------------------------------------------------------------
__global__ __launch_bounds__(128) void attn_spatial_kernel(
    const float* __restrict__ q, const float* __restrict__ kv,
    const float* __restrict__ tab, __half* __restrict__ o)
{
    __shared__ float ks[32][64];
    __shared__ float vs[32][64];
    int seq = blockIdx.z, h = blockIdx.y;
    int i = blockIdx.x * 128 + threadIdx.x;
    long tok0 = (long)seq * HW;

    float4 qr[16];
    const float4* qp = (const float4*)(q + (tok0 + i) * DIM + h * DHEAD);
#pragma unroll
    for (int c = 0; c < 16; c++) qr[c] = qp[c];

    float4 ov[16];
#pragma unroll
    for (int c = 0; c < 16; c++) ov[c] = make_float4(0.f, 0.f, 0.f, 0.f);
    float mval = -1e30f, l = 0.f;
    int yi = i >> 5, xi = i & 31;

    for (int j0 = 0; j0 < HW; j0 += 32) {
#pragma unroll
        for (int p = 0; p < 4; p++) {
            int qd = threadIdx.x + p * 128;
            int r = qd >> 4, c4 = (qd & 15) * 4;
            *(float4*)&ks[r][c4] = *(const float4*)(kv + (tok0 + j0 + r) * 2 * DIM + h * DHEAD + c4);
            *(float4*)&vs[r][c4] = *(const float4*)(kv + (tok0 + j0 + r) * 2 * DIM + DIM + h * DHEAD + c4);
        }
        __syncthreads();

        float s[32];
        int dyb = (yi - (j0 >> 5) + 31) * 63 + xi + 31;
#pragma unroll
        for (int jj = 0; jj < 32; jj++) {
            const float4* kp = (const float4*)ks[jj];
            float a = 0.f;
#pragma unroll
            for (int c = 0; c < 16; c++) {
                float4 k4 = kp[c];
                a += qr[c].x * k4.x + qr[c].y * k4.y + qr[c].z * k4.z + qr[c].w * k4.w;
            }
            s[jj] = a * SCALE_ATTN + __ldg(&tab[(dyb - jj) * 8 + h]);
        }
        float mt = mval;
#pragma unroll
        for (int jj = 0; jj < 32; jj++) mt = fmaxf(mt, s[jj]);
        float corr = __expf(mval - mt);
        mval = mt;
        l *= corr;
#pragma unroll
        for (int c = 0; c < 16; c++) {
            ov[c].x *= corr; ov[c].y *= corr; ov[c].z *= corr; ov[c].w *= corr;
        }
#pragma unroll
        for (int jj = 0; jj < 32; jj++) {
            float p = __expf(s[jj] - mt);
            l += p;
            const float4* vp = (const float4*)vs[jj];
#pragma unroll
            for (int c = 0; c < 16; c++) {
                float4 v4 = vp[c];
                ov[c].x += p * v4.x; ov[c].y += p * v4.y;
                ov[c].z += p * v4.z; ov[c].w += p * v4.w;
            }
        }
        __syncthreads();
    }
    float inv = 1.f / l;
    __half2* op = (__half2*)(o + (tok0 + i) * DIM + h * DHEAD);
#pragma unroll
    for (int c = 0; c < 16; c++) {
        op[c * 2]     = __floats2half2_rn(ov[c].x * inv, ov[c].y * inv);
        op[c * 2 + 1] = __floats2half2_rn(ov[c].z * inv, ov[c].w * inv);
    }
}

// ----------------------------------------------------------------------------
// Temporal attention (fp32 math, fp16 output)
// ----------------------------------------------------------------------------
__global__ __launch_bounds__(64) void attn_temporal_kernel(
    const float* __restrict__ q, const float* __restrict__ kv,
    const float* __restrict__ tab, __half* __restrict__ o)
{
    int seq = blockIdx.x;
    int h = threadIdx.x >> 3, i = threadIdx.x & 7;
    long base = (long)seq * FRAMES;

    float4 qr[16];
    const float4* qp = (const float4*)(q + (base + i) * DIM + h * DHEAD);
#pragma unroll
    for (int c = 0; c < 16; c++) qr[c] = qp[c];

    float s[8];
    float m = -1e30f;
#pragma unroll
    for (int j = 0; j < 8; j++) {
        const float4* kp = (const float4*)(kv + (base + j) * 2 * DIM + h * DHEAD);
        float a = 0.f;
#pragma unroll
        for (int c = 0; c < 16; c++) {
            float4 k4 = kp[c];
            a += qr[c].x * k4.x + qr[c].y * k4.y + qr[c].z * k4.z + qr[c].w * k4.w;
        }
        s[j] = a * SCALE_ATTN + __ldg(&tab[(i - j + 7) * 8 + h]);
        m = fmaxf(m, s[j]);
    }
    float l = 0.f;
#pragma unroll
    for (int j = 0; j < 8; j++) { s[j] = __expf(s[j] - m); l += s[j]; }
    float inv = 1.f / l;

    float4 ov[16];
#pragma unroll
    for (int c = 0; c < 16; c++) ov[c] = make_float4(0.f, 0.f, 0.f, 0.f);
#pragma unroll
    for (int j = 0; j < 8; j++) {
        float p = s[j] * inv;
        const float4* vp = (const float4*)(kv + (base + j) * 2 * DIM + DIM + h * DHEAD);
#pragma unroll
        for (int c = 0; c < 16; c++) {
            float4 v4 = vp[c];
            ov[c].x += p * v4.x; ov[c].y += p * v4.y;
            ov[c].z += p * v4.z; ov[c].w += p * v4.w;
        }
    }
    __half2* op = (__half2*)(o + (base + i) * DIM + h * DHEAD);
#pragma unroll
    for (int c = 0; c < 16; c++) {
        op[c * 2]     = __floats2half2_rn(ov[c].x, ov[c].y);
        op[c * 2 + 1] = __floats2half2_rn(ov[c].z, ov[c].w);
    }
}

// ----------------------------------------------------------------------------
// FF helpers
// ----------------------------------------------------------------------------
__global__ void geglu_kernel(const float* __restrict__ hdn, float* __restrict__ y) {
    int idx = blockIdx.x * 256 + threadIdx.x;
    int m = idx / FFI_P, c = idx % FFI_P;
    float v = 0.f;
    if (c < FFI) {
        float a  = hdn[(long)m * FF2_P + c];
        float gt = hdn[(long)m * FF2_P + FFI + c];
        v = a * (0.5f * gt * (1.f + erff(gt * 0.7071067811865475f)));
    }
    y[(long)m * FFI_P + c] = v;
}

__global__ __launch_bounds__(256) void shiftrms_kernel(
    const float* __restrict__ y, __half* __restrict__ yn, const float* __restrict__ g)
{
    __shared__ float buf[FFI];
    __shared__ float red[8];
    int m = blockIdx.x, t = threadIdx.x;
    int f = (m >> 10) & 7;
    float ss = 0.f;
    for (int c = t; c < FFI; c += 256) {
        float v;
        if (c < C1) v = y[(long)m * FFI_P + c];
        else        v = (f > 0) ? y[(long)(m - 1024) * FFI_P + c] : 0.f;
        buf[c] = v;
        ss += v * v;
    }
#pragma unroll
    for (int o = 16; o; o >>= 1) ss += __shfl_xor_sync(0xffffffffu, ss, o);
    if ((t & 31) == 0) red[t >> 5] = ss;
    __syncthreads();
    float tot = 0.f;
#pragma unroll
    for (int w = 0; w < 8; w++) tot += red[w];
    float inv = sqrtf(1365.0f) / fmaxf(sqrtf(tot), 1e-12f);
    for (int c = t; c < FFI_P; c += 256)
        yn[(long)m * FFI_P + c] = __float2half((c < FFI) ? buf[c] * inv * g[c] : 0.f);
}

// ----------------------------------------------------------------------------
// Host side
// ----------------------------------------------------------------------------
static float* symf(const void* symbol) {
    void* p = nullptr;
    cudaGetSymbolAddress(&p, symbol);
    return (float*)p;
}
static __half* symh(const void* symbol) {
    void* p = nullptr;
    cudaGetSymbolAddress(&p, symbol);
    return (__half*)p;
}

static void launch_hgemm(const __half* A, const __half* Bt, float* C,
                         const float* R, __half* Ch, int M, int N, int K, int flags) {
    dim3 grid(N / 64, M / 128);
    hgemm_kernel<<<grid, 256>>>(A, Bt, C, R, Ch, M, N, K, flags);
}

extern "C" void kernel_launch(void* const* d_in, const int* in_sizes, int n_in,
                              void* d_out, int out_size) {
    const float* x        = (const float*)d_in[0];
    const float* sa_gamma = (const float*)d_in[1];
    const float* sa_wq    = (const float*)d_in[2];
    const float* sa_wkv   = (const float*)d_in[3];
    const float* sa_wo    = (const float*)d_in[4];
    const float* ta_gamma = (const float*)d_in[5];
    const float* ta_wq    = (const float*)d_in[6];
    const float* ta_wkv   = (const float*)d_in[7];
    const float* ta_wo    = (const float*)d_in[8];
    const float* sp_w1    = (const float*)d_in[9];
    const float* sp_b1    = (const float*)d_in[10];
    const float* sp_w2    = (const float*)d_in[11];
    const float* sp_b2    = (const float*)d_in[12];
    const float* sp_w3    = (const float*)d_in[13];
    const float* sp_b3    = (const float*)d_in[14];
    const float* tp_w1    = (const float*)d_in[15];
    const float* tp_b1    = (const float*)d_in[16];
    const float* tp_w2    = (const float*)d_in[17];
    const float* tp_b2    = (const float*)d_in[18];
    const float* tp_w3    = (const float*)d_in[19];
    const float* tp_b3    = (const float*)d_in[20];
    const float* ff_win   = (const float*)d_in[21];
    const float* ff_gamma = (const float*)d_in[22];
    const float* ff_wout  = (const float*)d_in[23];
    float* out = (float*)d_out;

    float*  xs    = symf(g_xs);
    __half* xnh   = symh(g_xnh);
    float*  q     = symf(g_q);
    float*  kv    = symf(g_kv);
    __half* oh    = symh(g_oh);
    float*  res1  = symf(g_res1);
    float*  res2  = symf(g_res2);
    __half* res2h = symh(g_res2h);
    float*  ffd   = symf(g_ffd);
    float*  hdn   = symf(g_hdn);
    float*  yb    = symf(g_y);
    __half* ynh   = symh(g_ynh);
    float*  sptab = symf(g_sptab);
    float*  tptab = symf(g_tptab);
    __half* wt_saq   = symh(g_wt_saq);
    __half* wt_sakv  = symh(g_wt_sakv);
    __half* wt_sao   = symh(g_wt_sao);
    __half* wt_taq   = symh(g_wt_taq);
    __half* wt_takv  = symh(g_wt_takv);
    __half* wt_tao   = symh(g_wt_tao);
    __half* wt_ffin  = symh(g_wt_ffin);
    __half* wt_ffout = symh(g_wt_ffout);

    dim3 wblk(32, 8);
    // weight conversion (fp32 [K,N] -> fp16 [Np,Kp])
    wconv_kernel<<<dim3(16, 16),  wblk>>>(sa_wq,  wt_saq,  512, 512,  512, 512);
    wconv_kernel<<<dim3(16, 32),  wblk>>>(sa_wkv, wt_sakv, 512, 1024, 512, 1024);
    wconv_kernel<<<dim3(16, 16),  wblk>>>(sa_wo,  wt_sao,  512, 512,  512, 512);
    wconv_kernel<<<dim3(16, 16),  wblk>>>(ta_wq,  wt_taq,  512, 512,  512, 512);
    wconv_kernel<<<dim3(16, 32),  wblk>>>(ta_wkv, wt_takv, 512, 1024, 512, 1024);
    wconv_kernel<<<dim3(16, 16),  wblk>>>(ta_wo,  wt_tao,  512, 512,  512, 512);
    wconv_kernel<<<dim3(16, 88),  wblk>>>(ff_win, wt_ffin, 512, 2730, 512, 2816);
    wconv_kernel<<<dim3(44, 16),  wblk>>>(ff_wout, wt_ffout, 1365, 512, 1408, 512);

    // bias tables
    cpb2d_kernel<<<497, 256>>>(sp_w1, sp_b1, sp_w2, sp_b2, sp_w3, sp_b3, sptab);
    cpb1d_kernel<<<1, 256>>>(tp_w1, tp_b1, tp_w2, tp_b2, tp_w3, tp_b3, tptab);

    // input transpose: (b,c,f,h,w) -> tokens [16384,512]
    transpose_in_kernel<<<dim3(256, 16, 2), dim3(32, 8)>>>(x, xs);

    // ---- spatial attention ----
    rmsnorm512_kernel<<<NTOK, 128>>>(xs, xnh, sa_gamma, 0);
    launch_hgemm(xnh, wt_saq,  q,  nullptr, nullptr, NTOK, DIM,     DIM, 0);
    launch_hgemm(xnh, wt_sakv, kv, nullptr, nullptr, NTOK, 2 * DIM, DIM, 0);
    attn_spatial_kernel<<<dim3(8, 8, 16), 128>>>(q, kv, sptab, oh);
    launch_hgemm(oh, wt_sao, res1, xs, nullptr, NTOK, DIM, DIM, 1);

    // ---- temporal attention ----
    rmsnorm512_kernel<<<NTOK, 128>>>(res1, xnh, ta_gamma, 1);
    launch_hgemm(xnh, wt_taq,  q,  nullptr, nullptr, NTOK, DIM,     DIM, 0);
    launch_hgemm(xnh, wt_takv, kv, nullptr, nullptr, NTOK, 2 * DIM, DIM, 0);
    attn_temporal_kernel<<<SEQ_T, 64>>>(q, kv, tptab, oh);
    launch_hgemm(oh, wt_tao, res2, res1, res2h, NTOK, DIM, DIM, 1 | 2 | 4);

    // ---- feed forward ----
    launch_hgemm(res2h, wt_ffin, hdn, nullptr, nullptr, NTOK, FF2_P, DIM, 0);
    geglu_kernel<<<(NTOK * FFI_P) / 256, 256>>>(hdn, yb);
    shiftrms_kernel<<<NTOK, 256>>>(yb, ynh, ff_gamma);
    launch_hgemm(ynh, wt_ffout, ffd, res2, nullptr, NTOK, DIM, FFI_P, 1);

    // output transpose
    transpose_out_kernel<<<dim3(256, 16, 2), dim3(32, 8)>>>(ffd, out);
    (void)in_sizes; (void)n_in; (void)out_size;
}